// round 15
// baseline (speedup 1.0000x reference)
#include <cuda_runtime.h>
#include <math.h>
#include <stdint.h>

#define Bz 64
#define Tz 512
#define INz 1024
#define Hz 1024
#define Cz 512

#define RBLOCKS 128
#define RTHREADS 128

typedef unsigned long long ull;

// ---------------- persistent scratch ----------------------------------------
__device__ float d_xc[(size_t)Bz * Tz * Cz];            // xc, then c (in-place)
__device__ float d_g[(size_t)Bz * Tz * Hz];             // g = c @ Uc^T
__device__ float d_part[2][(size_t)RBLOCKS * 64 * 128]; // partials, double-buffered
__device__ float d_hTr2[2][Hz * 64];                    // h transposed, double-buffered
__device__ unsigned d_P[8 * 32];                        // partials-ready counters (128B stride)
__device__ unsigned d_Q[8 * 32];                        // h-ready counters       (128B stride)

// ---------------- f32x2 helpers ---------------------------------------------
__device__ __forceinline__ uint32_t saddr(const void* p) {
    return (uint32_t)__cvta_generic_to_shared(p);
}
__device__ __forceinline__ void lds2(ull& a, ull& b, uint32_t addr) {
    asm volatile("ld.shared.v2.u64 {%0,%1}, [%2];" : "=l"(a), "=l"(b) : "r"(addr));
}
__device__ __forceinline__ void ffma2(ull& d, ull a, ull b) {
    asm("fma.rn.f32x2 %0, %1, %2, %0;" : "+l"(d) : "l"(a), "l"(b));
}
__device__ __forceinline__ float2 u2f(ull v) {
    float2 r; asm("mov.b64 {%0,%1}, %2;" : "=f"(r.x), "=f"(r.y) : "l"(v)); return r;
}
__device__ __forceinline__ ull dup2(float f) {
    ull d; asm("mov.b64 %0, {%1,%1};" : "=l"(d) : "f"(f)); return d;
}

// ---------------- init: transpose h0 into buf 0, reset counters --------------
__global__ void init_kernel(const float* __restrict__ h0) {
    int idx = blockIdx.x * blockDim.x + threadIdx.x;   // 0 .. Hz*Bz-1
    if (idx < 8 * 32) { d_P[idx] = 0u; d_Q[idx] = 0u; }
    if (idx < Hz * Bz) {
        int n = idx >> 6, m = idx & 63;
        d_hTr2[0][n * 64 + m] = h0[m * Hz + n];
    }
}

// ---------------- EMA scan over T (in-place xc -> c), emit c_T --------------
__global__ void scan_kernel(const float* __restrict__ c0, float* __restrict__ outCT) {
    int idx = blockIdx.x * blockDim.x + threadIdx.x;   // 0 .. B*C-1
    int b = idx >> 9;
    int ch = idx & 511;
    float c = c0[idx];
    float* p = d_xc + (size_t)b * Tz * Cz + ch;
    const float a = 0.95f, na = 0.05f;
#pragma unroll 8
    for (int t = 0; t < Tz; ++t) {
        float v = p[t * Cz];
        c = na * c + a * v;
        p[t * Cz] = c;
    }
    outCT[idx] = c;
}

// ---------------- fp32x2 SGEMM (R9 proven): double-buffered, FFMA2 ----------
__global__ __launch_bounds__(256, 2) void sgemm_tn(
    const float* __restrict__ A, const float* __restrict__ Bw,
    const float* __restrict__ bias, float* __restrict__ Cout,
    int N, int K)
{
    __shared__ float As[2][16][132];
    __shared__ float Bs[2][16][132];
    const int tid = threadIdx.x;
    const int tx = tid & 15, ty = tid >> 4;
    const int m0 = blockIdx.x * 128, n0 = blockIdx.y * 128;
    const int lrow = tid >> 2;
    const int lkq  = (tid & 3) << 2;

    const float* Aptr0 = &A[(size_t)(m0 + lrow) * K + lkq];
    const float* Aptr1 = &A[(size_t)(m0 + lrow + 64) * K + lkq];
    const float* Bptr0 = &Bw[(size_t)(n0 + lrow) * K + lkq];
    const float* Bptr1 = &Bw[(size_t)(n0 + lrow + 64) * K + lkq];

    ull acc[4][8];
#pragma unroll
    for (int p = 0; p < 4; ++p)
#pragma unroll
        for (int j = 0; j < 8; ++j) acc[p][j] = 0ull;

    {
        float4 va0 = *reinterpret_cast<const float4*>(Aptr0);
        float4 va1 = *reinterpret_cast<const float4*>(Aptr1);
        float4 vb0 = *reinterpret_cast<const float4*>(Bptr0);
        float4 vb1 = *reinterpret_cast<const float4*>(Bptr1);
        As[0][lkq + 0][lrow] = va0.x; As[0][lkq + 1][lrow] = va0.y;
        As[0][lkq + 2][lrow] = va0.z; As[0][lkq + 3][lrow] = va0.w;
        As[0][lkq + 0][lrow + 64] = va1.x; As[0][lkq + 1][lrow + 64] = va1.y;
        As[0][lkq + 2][lrow + 64] = va1.z; As[0][lkq + 3][lrow + 64] = va1.w;
        Bs[0][lkq + 0][lrow] = vb0.x; Bs[0][lkq + 1][lrow] = vb0.y;
        Bs[0][lkq + 2][lrow] = vb0.z; Bs[0][lkq + 3][lrow] = vb0.w;
        Bs[0][lkq + 0][lrow + 64] = vb1.x; Bs[0][lkq + 1][lrow + 64] = vb1.y;
        Bs[0][lkq + 2][lrow + 64] = vb1.z; Bs[0][lkq + 3][lrow + 64] = vb1.w;
    }
    __syncthreads();

    const int nchunk = K >> 4;
    for (int c = 0; c < nchunk; ++c) {
        const int cur = c & 1, nxt = cur ^ 1;
        float4 va0, va1, vb0, vb1;
        const bool more = (c + 1 < nchunk);
        if (more) {
            int off = (c + 1) * 16;
            va0 = *reinterpret_cast<const float4*>(Aptr0 + off);
            va1 = *reinterpret_cast<const float4*>(Aptr1 + off);
            vb0 = *reinterpret_cast<const float4*>(Bptr0 + off);
            vb1 = *reinterpret_cast<const float4*>(Bptr1 + off);
        }
#pragma unroll
        for (int k = 0; k < 16; ++k) {
            ull a[4];
            lds2(a[0], a[1], saddr(&As[cur][k][ty * 4]));
            lds2(a[2], a[3], saddr(&As[cur][k][ty * 4 + 64]));
            float4 b0 = *reinterpret_cast<const float4*>(&Bs[cur][k][tx * 4]);
            float4 b1 = *reinterpret_cast<const float4*>(&Bs[cur][k][tx * 4 + 64]);
            ull bd[8];
            bd[0] = dup2(b0.x); bd[1] = dup2(b0.y); bd[2] = dup2(b0.z); bd[3] = dup2(b0.w);
            bd[4] = dup2(b1.x); bd[5] = dup2(b1.y); bd[6] = dup2(b1.z); bd[7] = dup2(b1.w);
#pragma unroll
            for (int p = 0; p < 4; ++p)
#pragma unroll
                for (int j = 0; j < 8; ++j)
                    ffma2(acc[p][j], a[p], bd[j]);
        }
        if (more) {
            As[nxt][lkq + 0][lrow] = va0.x; As[nxt][lkq + 1][lrow] = va0.y;
            As[nxt][lkq + 2][lrow] = va0.z; As[nxt][lkq + 3][lrow] = va0.w;
            As[nxt][lkq + 0][lrow + 64] = va1.x; As[nxt][lkq + 1][lrow + 64] = va1.y;
            As[nxt][lkq + 2][lrow + 64] = va1.z; As[nxt][lkq + 3][lrow + 64] = va1.w;
            Bs[nxt][lkq + 0][lrow] = vb0.x; Bs[nxt][lkq + 1][lrow] = vb0.y;
            Bs[nxt][lkq + 2][lrow] = vb0.z; Bs[nxt][lkq + 3][lrow] = vb0.w;
            Bs[nxt][lkq + 0][lrow + 64] = vb1.x; Bs[nxt][lkq + 1][lrow + 64] = vb1.y;
            Bs[nxt][lkq + 2][lrow + 64] = vb1.z; Bs[nxt][lkq + 3][lrow + 64] = vb1.w;
        }
        __syncthreads();
    }

    float bv[8] = {0.f, 0.f, 0.f, 0.f, 0.f, 0.f, 0.f, 0.f};
    if (bias) {
#pragma unroll
        for (int j = 0; j < 4; ++j) {
            bv[j]     = bias[n0 + tx * 4 + j];
            bv[4 + j] = bias[n0 + 64 + tx * 4 + j];
        }
    }
#pragma unroll
    for (int p = 0; p < 4; ++p) {
        int rbase = m0 + ((p < 2) ? (ty * 4 + 2 * p) : (64 + ty * 4 + 2 * (p - 2)));
        float2 q0 = u2f(acc[p][0]), q1 = u2f(acc[p][1]);
        float2 q2 = u2f(acc[p][2]), q3 = u2f(acc[p][3]);
        float2 q4 = u2f(acc[p][4]), q5 = u2f(acc[p][5]);
        float2 q6 = u2f(acc[p][6]), q7 = u2f(acc[p][7]);
        *reinterpret_cast<float4*>(&Cout[(size_t)rbase * N + n0 + tx * 4]) =
            make_float4(q0.x + bv[0], q1.x + bv[1], q2.x + bv[2], q3.x + bv[3]);
        *reinterpret_cast<float4*>(&Cout[(size_t)rbase * N + n0 + 64 + tx * 4]) =
            make_float4(q4.x + bv[4], q5.x + bv[5], q6.x + bv[6], q7.x + bv[7]);
        *reinterpret_cast<float4*>(&Cout[(size_t)(rbase + 1) * N + n0 + tx * 4]) =
            make_float4(q0.y + bv[0], q1.y + bv[1], q2.y + bv[2], q3.y + bv[3]);
        *reinterpret_cast<float4*>(&Cout[(size_t)(rbase + 1) * N + n0 + 64 + tx * 4]) =
            make_float4(q4.y + bv[4], q5.y + bv[5], q6.y + bv[6], q7.y + bv[7]);
    }
}

// ---------------- persistent recurrence: group-local sync, FFMA2 core -------
// grid 128 = 8 n-groups (nb) x 16 k-slices (kb).
// phase1(t): wait Q[kb>>1] >= 16*t  (h slice ready), write partials -> P[nb]++
// phase2(t): wait P[nb] >= 16*(t+1) (group partials ready), write h   -> Q[nb]++
// d_part and d_hTr2 double-buffered by t&1; counters monotonic.
__global__ __launch_bounds__(RTHREADS, 1) void recur_kernel(
    const float* __restrict__ Vh, float* __restrict__ out, float* __restrict__ outHT)
{
    __shared__ float vhs[64 * 128];   // Vh slice [k][n] (32KB, resident all steps)
    __shared__ float hs[64 * 64];     // h slice  [k][m] (16KB, restaged per step)

    const int tid = threadIdx.x;
    const int bid = blockIdx.x;
    const int nb = bid >> 4, kb = bid & 15;
    const int n0 = nb * 128, k0 = kb * 64;
    const int tx = tid & 15, ty = tid >> 4;
    const int gsrc = kb >> 1;                 // group producing our h slice

    for (int it = 0; it < 64; ++it) {
        int lin = it * 128 + tid;
        int n = lin >> 6, k = lin & 63;
        vhs[k * 128 + n] = Vh[(size_t)(n0 + n) * Hz + k0 + k];
    }

    // phase-2 assignment (group-local): m in [kb*4, kb*4+4), 4 consecutive n
    const int pm  = kb * 4 + (tid >> 5);      // batch row
    const int pnl = (tid & 31) * 4;           // n within tile [0,128)
    const int pn  = n0 + pnl;                 // global n

    __syncthreads();

    for (int t = 0; t < Tz; ++t) {
        const int par = t & 1;
        float* partW = &d_part[par][(size_t)bid * (64 * 128)];

        // ---- phase 1 gate: h slice for step t ready (group gsrc) ----
        if (t > 0) {
            if (tid == 0) {
                unsigned need = 16u * (unsigned)t;
                while (*(volatile unsigned*)&d_Q[gsrc * 32] < need) { __nanosleep(32); }
                __threadfence();   // acquire
            }
            __syncthreads();
        }

        // prefetch g_t for phase 2
        float4 s = __ldcg(reinterpret_cast<const float4*>(
            &d_g[((size_t)pm * Tz + t) * Hz + pn]));

        // stage h slice (coalesced float4) from buffer par
        {
            const float4* src = reinterpret_cast<const float4*>(
                &d_hTr2[par][(size_t)k0 * 64]);
            float4* dst = reinterpret_cast<float4*>(hs);
#pragma unroll
            for (int r = 0; r < 8; ++r) {
                int i = r * 128 + tid;
                dst[i] = __ldcg(&src[i]);
            }
        }
        __syncthreads();

        ull acc[4][8];
#pragma unroll
        for (int p = 0; p < 4; ++p)
#pragma unroll
            for (int j = 0; j < 8; ++j) acc[p][j] = 0ull;

#pragma unroll 8
        for (int k = 0; k < 64; ++k) {
            ull a[4];
            lds2(a[0], a[1], saddr(&hs[k * 64 + ty * 8]));
            lds2(a[2], a[3], saddr(&hs[k * 64 + ty * 8 + 4]));
            float4 b0 = *reinterpret_cast<const float4*>(&vhs[k * 128 + tx * 4]);
            float4 b1 = *reinterpret_cast<const float4*>(&vhs[k * 128 + 64 + tx * 4]);
            ull bd[8];
            bd[0] = dup2(b0.x); bd[1] = dup2(b0.y); bd[2] = dup2(b0.z); bd[3] = dup2(b0.w);
            bd[4] = dup2(b1.x); bd[5] = dup2(b1.y); bd[6] = dup2(b1.z); bd[7] = dup2(b1.w);
#pragma unroll
            for (int p = 0; p < 4; ++p)
#pragma unroll
                for (int j = 0; j < 8; ++j)
                    ffma2(acc[p][j], a[p], bd[j]);
        }

#pragma unroll
        for (int p = 0; p < 4; ++p) {
            int m0 = ty * 8 + 2 * p;
            float2 q0 = u2f(acc[p][0]), q1 = u2f(acc[p][1]);
            float2 q2 = u2f(acc[p][2]), q3 = u2f(acc[p][3]);
            float2 q4 = u2f(acc[p][4]), q5 = u2f(acc[p][5]);
            float2 q6 = u2f(acc[p][6]), q7 = u2f(acc[p][7]);
            __stcg(reinterpret_cast<float4*>(&partW[m0 * 128 + tx * 4]),
                   make_float4(q0.x, q1.x, q2.x, q3.x));
            __stcg(reinterpret_cast<float4*>(&partW[m0 * 128 + 64 + tx * 4]),
                   make_float4(q4.x, q5.x, q6.x, q7.x));
            __stcg(reinterpret_cast<float4*>(&partW[(m0 + 1) * 128 + tx * 4]),
                   make_float4(q0.y, q1.y, q2.y, q3.y));
            __stcg(reinterpret_cast<float4*>(&partW[(m0 + 1) * 128 + 64 + tx * 4]),
                   make_float4(q4.y, q5.y, q6.y, q7.y));
        }

        // signal partials ready
        __threadfence();
        __syncthreads();
        if (tid == 0) atomicAdd(&d_P[nb * 32], 1u);

        // ---- phase 2 gate: all 16 group partials ready ----
        if (tid == 0) {
            unsigned need = 16u * (unsigned)(t + 1);
            while (*(volatile unsigned*)&d_P[nb * 32] < need) { __nanosleep(32); }
            __threadfence();   // acquire
        }
        __syncthreads();

        // reduce 16 partials (own group) + g_t, tanh
#pragma unroll
        for (int k2 = 0; k2 < 16; ++k2) {
            float4 p = __ldcg(reinterpret_cast<const float4*>(
                &d_part[par][(size_t)(nb * 16 + k2) * (64 * 128) + pm * 128 + pnl]));
            s.x += p.x; s.y += p.y; s.z += p.z; s.w += p.w;
        }
        float4 hv = make_float4(tanhf(s.x), tanhf(s.y), tanhf(s.z), tanhf(s.w));

        *reinterpret_cast<float4*>(&out[((size_t)pm * Tz + t) * Hz + pn]) = hv;
        float* hb = d_hTr2[par ^ 1];
        __stcg(&hb[(pn + 0) * 64 + pm], hv.x);
        __stcg(&hb[(pn + 1) * 64 + pm], hv.y);
        __stcg(&hb[(pn + 2) * 64 + pm], hv.z);
        __stcg(&hb[(pn + 3) * 64 + pm], hv.w);
        if (t == Tz - 1) {
            *reinterpret_cast<float4*>(&outHT[(size_t)pm * Hz + pn]) = hv;
        }

        // signal h ready
        __threadfence();
        __syncthreads();
        if (tid == 0) atomicAdd(&d_Q[nb * 32], 1u);
    }
}

// ---------------- launch ----------------------------------------------------
extern "C" void kernel_launch(void* const* d_in, const int* in_sizes, int n_in,
                              void* d_out, int out_size) {
    const float* x  = (const float*)d_in[0];
    const float* h0 = (const float*)d_in[1];
    const float* c0 = (const float*)d_in[2];
    const float* Wx = (const float*)d_in[3];
    const float* bx = (const float*)d_in[4];
    const float* Uc = (const float*)d_in[5];
    const float* Vh = (const float*)d_in[6];

    float* out   = (float*)d_out;                       // [B,T,H]
    float* outHT = out + (size_t)Bz * Tz * Hz;          // [B,H]
    float* outCT = outHT + (size_t)Bz * Hz;             // [B,C]

    float *dxc, *dg;
    cudaGetSymbolAddress((void**)&dxc, d_xc);
    cudaGetSymbolAddress((void**)&dg, d_g);

    // 1) init: transpose h0 into buf 0, reset counters
    init_kernel<<<(Hz * Bz + 255) / 256, 256>>>(h0);

    // 2) xc = x @ Wx^T + bx   (M=32768, N=512, K=1024)
    sgemm_tn<<<dim3((Bz * Tz) / 128, Cz / 128), 256>>>(x, Wx, bx, dxc, Cz, INz);

    // 3) EMA scan: xc -> c (in place), write c_T
    scan_kernel<<<(Bz * Cz) / 256, 256>>>(c0, outCT);

    // 4) g = c @ Uc^T   (M=32768, N=1024, K=512)
    sgemm_tn<<<dim3((Bz * Tz) / 128, Hz / 128), 256>>>(dxc, Uc, nullptr, dg, Hz, Cz);

    // 5) recurrence: h_t = tanh(g_t + h_{t-1} @ Vh^T), all 512 steps
    recur_kernel<<<RBLOCKS, RTHREADS>>>(Vh, out, outHT);
}

// round 16
// speedup vs baseline: 1.0033x; 1.0033x over previous
#include <cuda_runtime.h>
#include <math.h>
#include <stdint.h>

#define Bz 64
#define Tz 512
#define INz 1024
#define Hz 1024
#define Cz 512

#define RBLOCKS 128
#define RTHREADS 128

typedef unsigned long long ull;

// ---------------- persistent scratch ----------------------------------------
__device__ float d_xc[(size_t)Bz * Tz * Cz];            // xc, then c (in-place)
__device__ float d_g[(size_t)Bz * Tz * Hz];             // g = c @ Uc^T
__device__ float d_part[2][(size_t)RBLOCKS * 64 * 128]; // partials, double-buffered
__device__ float d_hTr2[2][Hz * 64];                    // h transposed, double-buffered
__device__ unsigned d_P[8 * 32];                        // partials-ready counters (128B stride)
__device__ unsigned d_Q[8 * 32];                        // h-ready counters       (128B stride)

// ---------------- f32x2 helpers ---------------------------------------------
__device__ __forceinline__ uint32_t saddr(const void* p) {
    return (uint32_t)__cvta_generic_to_shared(p);
}
__device__ __forceinline__ void lds2(ull& a, ull& b, uint32_t addr) {
    asm volatile("ld.shared.v2.u64 {%0,%1}, [%2];" : "=l"(a), "=l"(b) : "r"(addr));
}
__device__ __forceinline__ void ffma2(ull& d, ull a, ull b) {
    asm("fma.rn.f32x2 %0, %1, %2, %0;" : "+l"(d) : "l"(a), "l"(b));
}
__device__ __forceinline__ float2 u2f(ull v) {
    float2 r; asm("mov.b64 {%0,%1}, %2;" : "=f"(r.x), "=f"(r.y) : "l"(v)); return r;
}
__device__ __forceinline__ ull dup2(float f) {
    ull d; asm("mov.b64 %0, {%1,%1};" : "=l"(d) : "f"(f)); return d;
}

// ---------------- init: transpose h0 into buf 0, reset counters --------------
__global__ void init_kernel(const float* __restrict__ h0) {
    int idx = blockIdx.x * blockDim.x + threadIdx.x;   // 0 .. Hz*Bz-1
    if (idx < 8 * 32) { d_P[idx] = 0u; d_Q[idx] = 0u; }
    if (idx < Hz * Bz) {
        int n = idx >> 6, m = idx & 63;
        d_hTr2[0][n * 64 + m] = h0[m * Hz + n];
    }
}

// ---------------- EMA scan over T (in-place xc -> c), emit c_T --------------
__global__ void scan_kernel(const float* __restrict__ c0, float* __restrict__ outCT) {
    int idx = blockIdx.x * blockDim.x + threadIdx.x;   // 0 .. B*C-1
    int b = idx >> 9;
    int ch = idx & 511;
    float c = c0[idx];
    float* p = d_xc + (size_t)b * Tz * Cz + ch;
    const float a = 0.95f, na = 0.05f;
#pragma unroll 8
    for (int t = 0; t < Tz; ++t) {
        float v = p[t * Cz];
        c = na * c + a * v;
        p[t * Cz] = c;
    }
    outCT[idx] = c;
}

// ---------------- fp32x2 SGEMM (R9 proven): double-buffered, FFMA2 ----------
__global__ __launch_bounds__(256, 2) void sgemm_tn(
    const float* __restrict__ A, const float* __restrict__ Bw,
    const float* __restrict__ bias, float* __restrict__ Cout,
    int N, int K)
{
    __shared__ float As[2][16][132];
    __shared__ float Bs[2][16][132];
    const int tid = threadIdx.x;
    const int tx = tid & 15, ty = tid >> 4;
    const int m0 = blockIdx.x * 128, n0 = blockIdx.y * 128;
    const int lrow = tid >> 2;
    const int lkq  = (tid & 3) << 2;

    const float* Aptr0 = &A[(size_t)(m0 + lrow) * K + lkq];
    const float* Aptr1 = &A[(size_t)(m0 + lrow + 64) * K + lkq];
    const float* Bptr0 = &Bw[(size_t)(n0 + lrow) * K + lkq];
    const float* Bptr1 = &Bw[(size_t)(n0 + lrow + 64) * K + lkq];

    ull acc[4][8];
#pragma unroll
    for (int p = 0; p < 4; ++p)
#pragma unroll
        for (int j = 0; j < 8; ++j) acc[p][j] = 0ull;

    {
        float4 va0 = *reinterpret_cast<const float4*>(Aptr0);
        float4 va1 = *reinterpret_cast<const float4*>(Aptr1);
        float4 vb0 = *reinterpret_cast<const float4*>(Bptr0);
        float4 vb1 = *reinterpret_cast<const float4*>(Bptr1);
        As[0][lkq + 0][lrow] = va0.x; As[0][lkq + 1][lrow] = va0.y;
        As[0][lkq + 2][lrow] = va0.z; As[0][lkq + 3][lrow] = va0.w;
        As[0][lkq + 0][lrow + 64] = va1.x; As[0][lkq + 1][lrow + 64] = va1.y;
        As[0][lkq + 2][lrow + 64] = va1.z; As[0][lkq + 3][lrow + 64] = va1.w;
        Bs[0][lkq + 0][lrow] = vb0.x; Bs[0][lkq + 1][lrow] = vb0.y;
        Bs[0][lkq + 2][lrow] = vb0.z; Bs[0][lkq + 3][lrow] = vb0.w;
        Bs[0][lkq + 0][lrow + 64] = vb1.x; Bs[0][lkq + 1][lrow + 64] = vb1.y;
        Bs[0][lkq + 2][lrow + 64] = vb1.z; Bs[0][lkq + 3][lrow + 64] = vb1.w;
    }
    __syncthreads();

    const int nchunk = K >> 4;
    for (int c = 0; c < nchunk; ++c) {
        const int cur = c & 1, nxt = cur ^ 1;
        float4 va0, va1, vb0, vb1;
        const bool more = (c + 1 < nchunk);
        if (more) {
            int off = (c + 1) * 16;
            va0 = *reinterpret_cast<const float4*>(Aptr0 + off);
            va1 = *reinterpret_cast<const float4*>(Aptr1 + off);
            vb0 = *reinterpret_cast<const float4*>(Bptr0 + off);
            vb1 = *reinterpret_cast<const float4*>(Bptr1 + off);
        }
#pragma unroll
        for (int k = 0; k < 16; ++k) {
            ull a[4];
            lds2(a[0], a[1], saddr(&As[cur][k][ty * 4]));
            lds2(a[2], a[3], saddr(&As[cur][k][ty * 4 + 64]));
            float4 b0 = *reinterpret_cast<const float4*>(&Bs[cur][k][tx * 4]);
            float4 b1 = *reinterpret_cast<const float4*>(&Bs[cur][k][tx * 4 + 64]);
            ull bd[8];
            bd[0] = dup2(b0.x); bd[1] = dup2(b0.y); bd[2] = dup2(b0.z); bd[3] = dup2(b0.w);
            bd[4] = dup2(b1.x); bd[5] = dup2(b1.y); bd[6] = dup2(b1.z); bd[7] = dup2(b1.w);
#pragma unroll
            for (int p = 0; p < 4; ++p)
#pragma unroll
                for (int j = 0; j < 8; ++j)
                    ffma2(acc[p][j], a[p], bd[j]);
        }
        if (more) {
            As[nxt][lkq + 0][lrow] = va0.x; As[nxt][lkq + 1][lrow] = va0.y;
            As[nxt][lkq + 2][lrow] = va0.z; As[nxt][lkq + 3][lrow] = va0.w;
            As[nxt][lkq + 0][lrow + 64] = va1.x; As[nxt][lkq + 1][lrow + 64] = va1.y;
            As[nxt][lkq + 2][lrow + 64] = va1.z; As[nxt][lkq + 3][lrow + 64] = va1.w;
            Bs[nxt][lkq + 0][lrow] = vb0.x; Bs[nxt][lkq + 1][lrow] = vb0.y;
            Bs[nxt][lkq + 2][lrow] = vb0.z; Bs[nxt][lkq + 3][lrow] = vb0.w;
            Bs[nxt][lkq + 0][lrow + 64] = vb1.x; Bs[nxt][lkq + 1][lrow + 64] = vb1.y;
            Bs[nxt][lkq + 2][lrow + 64] = vb1.z; Bs[nxt][lkq + 3][lrow + 64] = vb1.w;
        }
        __syncthreads();
    }

    float bv[8] = {0.f, 0.f, 0.f, 0.f, 0.f, 0.f, 0.f, 0.f};
    if (bias) {
#pragma unroll
        for (int j = 0; j < 4; ++j) {
            bv[j]     = bias[n0 + tx * 4 + j];
            bv[4 + j] = bias[n0 + 64 + tx * 4 + j];
        }
    }
#pragma unroll
    for (int p = 0; p < 4; ++p) {
        int rbase = m0 + ((p < 2) ? (ty * 4 + 2 * p) : (64 + ty * 4 + 2 * (p - 2)));
        float2 q0 = u2f(acc[p][0]), q1 = u2f(acc[p][1]);
        float2 q2 = u2f(acc[p][2]), q3 = u2f(acc[p][3]);
        float2 q4 = u2f(acc[p][4]), q5 = u2f(acc[p][5]);
        float2 q6 = u2f(acc[p][6]), q7 = u2f(acc[p][7]);
        *reinterpret_cast<float4*>(&Cout[(size_t)rbase * N + n0 + tx * 4]) =
            make_float4(q0.x + bv[0], q1.x + bv[1], q2.x + bv[2], q3.x + bv[3]);
        *reinterpret_cast<float4*>(&Cout[(size_t)rbase * N + n0 + 64 + tx * 4]) =
            make_float4(q4.x + bv[4], q5.x + bv[5], q6.x + bv[6], q7.x + bv[7]);
        *reinterpret_cast<float4*>(&Cout[(size_t)(rbase + 1) * N + n0 + tx * 4]) =
            make_float4(q0.y + bv[0], q1.y + bv[1], q2.y + bv[2], q3.y + bv[3]);
        *reinterpret_cast<float4*>(&Cout[(size_t)(rbase + 1) * N + n0 + 64 + tx * 4]) =
            make_float4(q4.y + bv[4], q5.y + bv[5], q6.y + bv[6], q7.y + bv[7]);
    }
}

// ---------------- persistent recurrence: group-local sync, hot-spin gates ----
// grid 128 = 8 n-groups (nb) x 16 k-slices (kb).
// phase1(t): wait Q[kb>>1] >= 16*t  (h slice ready), write partials -> P[nb]++
// phase2(t): wait P[nb] >= 16*(t+1) (group partials ready), write h   -> Q[nb]++
// d_part and d_hTr2 double-buffered by t&1; counters monotonic.
__global__ __launch_bounds__(RTHREADS, 1) void recur_kernel(
    const float* __restrict__ Vh, float* __restrict__ out, float* __restrict__ outHT)
{
    __shared__ float vhs[64 * 128];   // Vh slice [k][n] (32KB, resident all steps)
    __shared__ float hs[64 * 64];     // h slice  [k][m] (16KB, restaged per step)

    const int tid = threadIdx.x;
    const int bid = blockIdx.x;
    const int nb = bid >> 4, kb = bid & 15;
    const int n0 = nb * 128, k0 = kb * 64;
    const int tx = tid & 15, ty = tid >> 4;
    const int gsrc = kb >> 1;                 // group producing our h slice

    for (int it = 0; it < 64; ++it) {
        int lin = it * 128 + tid;
        int n = lin >> 6, k = lin & 63;
        vhs[k * 128 + n] = Vh[(size_t)(n0 + n) * Hz + k0 + k];
    }

    // phase-2 assignment (group-local): m in [kb*4, kb*4+4), 4 consecutive n
    const int pm  = kb * 4 + (tid >> 5);      // batch row
    const int pnl = (tid & 31) * 4;           // n within tile [0,128)
    const int pn  = n0 + pnl;                 // global n

    __syncthreads();

    for (int t = 0; t < Tz; ++t) {
        const int par = t & 1;
        float* partW = &d_part[par][(size_t)bid * (64 * 128)];

        // ---- phase 1 gate: h slice for step t ready (group gsrc) ----
        if (t > 0) {
            if (tid == 0) {
                unsigned need = 16u * (unsigned)t;
                while (*(volatile unsigned*)&d_Q[gsrc * 32] < need) { }
                __threadfence();   // acquire
            }
            __syncthreads();
        }

        // prefetch g_t for phase 2
        float4 s = __ldcg(reinterpret_cast<const float4*>(
            &d_g[((size_t)pm * Tz + t) * Hz + pn]));

        // stage h slice (coalesced float4) from buffer par
        {
            const float4* src = reinterpret_cast<const float4*>(
                &d_hTr2[par][(size_t)k0 * 64]);
            float4* dst = reinterpret_cast<float4*>(hs);
#pragma unroll
            for (int r = 0; r < 8; ++r) {
                int i = r * 128 + tid;
                dst[i] = __ldcg(&src[i]);
            }
        }
        __syncthreads();

        ull acc[4][8];
#pragma unroll
        for (int p = 0; p < 4; ++p)
#pragma unroll
            for (int j = 0; j < 8; ++j) acc[p][j] = 0ull;

#pragma unroll 8
        for (int k = 0; k < 64; ++k) {
            ull a[4];
            lds2(a[0], a[1], saddr(&hs[k * 64 + ty * 8]));
            lds2(a[2], a[3], saddr(&hs[k * 64 + ty * 8 + 4]));
            float4 b0 = *reinterpret_cast<const float4*>(&vhs[k * 128 + tx * 4]);
            float4 b1 = *reinterpret_cast<const float4*>(&vhs[k * 128 + 64 + tx * 4]);
            ull bd[8];
            bd[0] = dup2(b0.x); bd[1] = dup2(b0.y); bd[2] = dup2(b0.z); bd[3] = dup2(b0.w);
            bd[4] = dup2(b1.x); bd[5] = dup2(b1.y); bd[6] = dup2(b1.z); bd[7] = dup2(b1.w);
#pragma unroll
            for (int p = 0; p < 4; ++p)
#pragma unroll
                for (int j = 0; j < 8; ++j)
                    ffma2(acc[p][j], a[p], bd[j]);
        }

#pragma unroll
        for (int p = 0; p < 4; ++p) {
            int m0 = ty * 8 + 2 * p;
            float2 q0 = u2f(acc[p][0]), q1 = u2f(acc[p][1]);
            float2 q2 = u2f(acc[p][2]), q3 = u2f(acc[p][3]);
            float2 q4 = u2f(acc[p][4]), q5 = u2f(acc[p][5]);
            float2 q6 = u2f(acc[p][6]), q7 = u2f(acc[p][7]);
            __stcg(reinterpret_cast<float4*>(&partW[m0 * 128 + tx * 4]),
                   make_float4(q0.x, q1.x, q2.x, q3.x));
            __stcg(reinterpret_cast<float4*>(&partW[m0 * 128 + 64 + tx * 4]),
                   make_float4(q4.x, q5.x, q6.x, q7.x));
            __stcg(reinterpret_cast<float4*>(&partW[(m0 + 1) * 128 + tx * 4]),
                   make_float4(q0.y, q1.y, q2.y, q3.y));
            __stcg(reinterpret_cast<float4*>(&partW[(m0 + 1) * 128 + 64 + tx * 4]),
                   make_float4(q4.y, q5.y, q6.y, q7.y));
        }

        // signal partials ready
        __threadfence();
        __syncthreads();
        if (tid == 0) atomicAdd(&d_P[nb * 32], 1u);

        // ---- phase 2 gate: all 16 group partials ready ----
        if (tid == 0) {
            unsigned need = 16u * (unsigned)(t + 1);
            while (*(volatile unsigned*)&d_P[nb * 32] < need) { }
            __threadfence();   // acquire
        }
        __syncthreads();

        // reduce 16 partials (own group) + g_t, tanh
#pragma unroll
        for (int k2 = 0; k2 < 16; ++k2) {
            float4 p = __ldcg(reinterpret_cast<const float4*>(
                &d_part[par][(size_t)(nb * 16 + k2) * (64 * 128) + pm * 128 + pnl]));
            s.x += p.x; s.y += p.y; s.z += p.z; s.w += p.w;
        }
        float4 hv = make_float4(tanhf(s.x), tanhf(s.y), tanhf(s.z), tanhf(s.w));

        *reinterpret_cast<float4*>(&out[((size_t)pm * Tz + t) * Hz + pn]) = hv;
        float* hb = d_hTr2[par ^ 1];
        __stcg(&hb[(pn + 0) * 64 + pm], hv.x);
        __stcg(&hb[(pn + 1) * 64 + pm], hv.y);
        __stcg(&hb[(pn + 2) * 64 + pm], hv.z);
        __stcg(&hb[(pn + 3) * 64 + pm], hv.w);
        if (t == Tz - 1) {
            *reinterpret_cast<float4*>(&outHT[(size_t)pm * Hz + pn]) = hv;
        }

        // signal h ready
        __threadfence();
        __syncthreads();
        if (tid == 0) atomicAdd(&d_Q[nb * 32], 1u);
    }
}

// ---------------- launch ----------------------------------------------------
extern "C" void kernel_launch(void* const* d_in, const int* in_sizes, int n_in,
                              void* d_out, int out_size) {
    const float* x  = (const float*)d_in[0];
    const float* h0 = (const float*)d_in[1];
    const float* c0 = (const float*)d_in[2];
    const float* Wx = (const float*)d_in[3];
    const float* bx = (const float*)d_in[4];
    const float* Uc = (const float*)d_in[5];
    const float* Vh = (const float*)d_in[6];

    float* out   = (float*)d_out;                       // [B,T,H]
    float* outHT = out + (size_t)Bz * Tz * Hz;          // [B,H]
    float* outCT = outHT + (size_t)Bz * Hz;             // [B,C]

    float *dxc, *dg;
    cudaGetSymbolAddress((void**)&dxc, d_xc);
    cudaGetSymbolAddress((void**)&dg, d_g);

    // 1) init: transpose h0 into buf 0, reset counters
    init_kernel<<<(Hz * Bz + 255) / 256, 256>>>(h0);

    // 2) xc = x @ Wx^T + bx   (M=32768, N=512, K=1024)
    sgemm_tn<<<dim3((Bz * Tz) / 128, Cz / 128), 256>>>(x, Wx, bx, dxc, Cz, INz);

    // 3) EMA scan: xc -> c (in place), write c_T
    scan_kernel<<<(Bz * Cz) / 256, 256>>>(c0, outCT);

    // 4) g = c @ Uc^T   (M=32768, N=1024, K=512)
    sgemm_tn<<<dim3((Bz * Tz) / 128, Hz / 128), 256>>>(dxc, Uc, nullptr, dg, Hz, Cz);

    // 5) recurrence: h_t = tanh(g_t + h_{t-1} @ Vh^T), all 512 steps
    recur_kernel<<<RBLOCKS, RTHREADS>>>(Vh, out, outHT);
}